// round 4
// baseline (speedup 1.0000x reference)
#include <cuda_runtime.h>

#define N_ITEMS  262144
#define DIM      128
#define NCB      3
#define KCW      256
#define MT       64          // items per CTA
#define NTHREADS 512
#define RS       132         // smem row stride (floats), breaks bank conflicts

// smem floats: cb 33792 | rres 8448 | cc 256 | rrs 64 | redv 2048 | redi 2048 | best 192
#define SMEM_FLOATS (KCW*RS + MT*RS + KCW + MT + MT*32 + MT*32 + NCB*MT)
#define SMEM_BYTES  (SMEM_FLOATS * 4)

__global__ __launch_bounds__(NTHREADS, 1)
void rvq_kernel(const float* __restrict__ x,
                const float* __restrict__ codebooks,
                float* __restrict__ out, int mode)
{
    extern __shared__ float sm[];
    float* cb   = sm;
    float* rres = cb   + KCW * RS;
    float* cc   = rres + MT * RS;
    float* rrs  = cc   + KCW;
    float* redv = rrs  + MT;
    int*   redi = (int*)(redv + MT * 32);
    int*   best = redi + MT * 32;

    const int t  = threadIdx.x;
    const int ig = t & 15;    // item group: items ig + 16u, u<4
    const int cg = t >> 4;    // cw group:   cws   cg + 32v, v<8   (cg 0..31)
    const int itemBase = blockIdx.x * MT;

    // ---- load x tile into rres (residual starts as x) ----
    {
        const float4* xg = (const float4*)(x + (size_t)itemBase * DIM);
        #pragma unroll
        for (int n = 0; n < (MT * DIM / 4) / NTHREADS; n++) {   // 4
            int idx = t + NTHREADS * n;
            int row = idx >> 5;
            int c4  = idx & 31;
            float4 v = xg[idx];
            float* dr = &rres[row * RS + 4 * c4];
            dr[0] = v.x; dr[1] = v.y; dr[2] = v.z; dr[3] = v.w;
        }
    }

    for (int stage = 0; stage < NCB; stage++) {
        __syncthreads();
        // ---- load codebook[stage] into smem ----
        {
            const float4* cgm = (const float4*)(codebooks + (size_t)stage * KCW * DIM);
            #pragma unroll
            for (int n = 0; n < (KCW * DIM / 4) / NTHREADS; n++) {  // 16
                int idx = t + NTHREADS * n;
                int row = idx >> 5;
                int c4  = idx & 31;
                float4 v = cgm[idx];
                float* d = &cb[row * RS + 4 * c4];
                d[0] = v.x; d[1] = v.y; d[2] = v.z; d[3] = v.w;
            }
        }
        __syncthreads();

        // ---- cc[j] = ||c_j||^2, double then one fp32 round ----
        if (t < KCW) {
            double s = 0.0;
            const float* rowp = &cb[t * RS];
            #pragma unroll 8
            for (int k = 0; k < DIM; k++) {
                double v = (double)rowp[k];
                s += v * v;
            }
            cc[t] = (float)s;
        }
        // ---- rrs[i] = ||r_i||^2, double then one fp32 round ----
        if (t < MT) {
            double s = 0.0;
            const float* rowp = &rres[t * RS];
            #pragma unroll 8
            for (int k = 0; k < DIM; k++) {
                double v = (double)rowp[k];
                s += v * v;
            }
            rrs[t] = (float)s;
        }
        __syncthreads();

        // ---- 4x8 register tile, strict sequential FMA chain over k ascending ----
        float acc[4][8];
        #pragma unroll
        for (int u = 0; u < 4; u++)
            #pragma unroll
            for (int v = 0; v < 8; v++) acc[u][v] = 0.f;

        #pragma unroll 1
        for (int k4 = 0; k4 < DIM / 4; k4++) {
            float rv[4][4], cv[8][4];
            #pragma unroll
            for (int u = 0; u < 4; u++)
                *(float4*)rv[u] = *(const float4*)&rres[(ig + 16 * u) * RS + 4 * k4];
            #pragma unroll
            for (int v = 0; v < 8; v++)
                *(float4*)cv[v] = *(const float4*)&cb[(cg + 32 * v) * RS + 4 * k4];
            #pragma unroll
            for (int kk = 0; kk < 4; kk++)
                #pragma unroll
                for (int u = 0; u < 4; u++)
                    #pragma unroll
                    for (int v = 0; v < 8; v++)
                        acc[u][v] = __fmaf_rn(rv[u][kk], cv[v][kk], acc[u][v]);
        }

        // ---- per-thread argmin of d2 = fl(fl(rr - 2*dot) + cc) ----
        #pragma unroll
        for (int u = 0; u < 4; u++) {
            int item = ig + 16 * u;
            float rrv = rrs[item];
            float bv = 3.0e38f; int bi = KCW;
            #pragma unroll
            for (int v = 0; v < 8; v++) {
                int cw = cg + 32 * v;          // ascending within thread
                float d2 = __fadd_rn(__fmaf_rn(-2.0f, acc[u][v], rrv), cc[cw]);
                if (d2 < bv) { bv = d2; bi = cw; }   // strict <: keeps lowest cw
            }
            redv[cg * MT + item] = bv;   // transposed: conflict-free STS
            redi[cg * MT + item] = bi;
        }
        __syncthreads();

        // ---- reduce 32 slots per item; tie-break: smaller index ----
        if (t < MT) {
            float bv = 3.0e38f; int bi = KCW;
            #pragma unroll 4
            for (int s2 = 0; s2 < 32; s2++) {
                float v  = redv[s2 * MT + t];
                int   i2 = redi[s2 * MT + t];
                if (v < bv || (v == bv && i2 < bi)) { bv = v; bi = i2; }
            }
            best[stage * MT + t] = bi;
            size_t gi = (size_t)(itemBase + t);
            if (mode == 0)      out[gi * 3 + stage] = (float)bi;
            else if (mode == 2) ((int*)out)[gi * 3 + stage] = bi;
        }
        __syncthreads();

        // ---- residual -= chosen codeword ----
        if (stage < NCB - 1) {   // last residual not needed
            #pragma unroll
            for (int n = 0; n < (MT * DIM / 4) / NTHREADS; n++) {   // 4
                int e    = t + NTHREADS * n;
                int item = e >> 5;
                int c4   = e & 31;
                int bi   = best[stage * MT + item];
                float4 cv = *(const float4*)&cb[bi * RS + 4 * c4];
                float4 rv = *(float4*)&rres[item * RS + 4 * c4];
                rv.x = __fsub_rn(rv.x, cv.x); rv.y = __fsub_rn(rv.y, cv.y);
                rv.z = __fsub_rn(rv.z, cv.z); rv.w = __fsub_rn(rv.w, cv.w);
                *(float4*)&rres[item * RS + 4 * c4] = rv;
            }
        }
    }
    __syncthreads();

    // ---- quantized = (c0[i0] + c1[i1]) + c2[i2], reference order ----
    if (mode != 2) {
        float* outq = (mode == 0) ? (out + (size_t)N_ITEMS * 3) : out;
        float4* oq4 = (float4*)outq;
        const float4* cb4 = (const float4*)codebooks;
        #pragma unroll
        for (int n = 0; n < (MT * DIM / 4) / NTHREADS; n++) {   // 4
            int e    = t + NTHREADS * n;
            int item = e >> 5;
            int c4   = e & 31;
            int i0 = best[0 * MT + item];
            int i1 = best[1 * MT + item];
            int i2 = best[2 * MT + item];
            float4 q0 = cb4[(size_t)(0 * KCW + i0) * (DIM / 4) + c4];
            float4 q1 = cb4[(size_t)(1 * KCW + i1) * (DIM / 4) + c4];
            float4 q2 = cb4[(size_t)(2 * KCW + i2) * (DIM / 4) + c4];
            float4 q;
            q.x = __fadd_rn(__fadd_rn(q0.x, q1.x), q2.x);
            q.y = __fadd_rn(__fadd_rn(q0.y, q1.y), q2.y);
            q.z = __fadd_rn(__fadd_rn(q0.z, q1.z), q2.z);
            q.w = __fadd_rn(__fadd_rn(q0.w, q1.w), q2.w);
            oq4[(size_t)itemBase * (DIM / 4) + e] = q;
        }
    }
}

extern "C" void kernel_launch(void* const* d_in, const int* in_sizes, int n_in,
                              void* d_out, int out_size)
{
    const float* x   = (const float*)d_in[0];
    const float* cbk = (const float*)d_in[1];
    if (n_in >= 2 && in_sizes[0] == NCB * KCW * DIM && in_sizes[1] == N_ITEMS * DIM) {
        const float* tmp = x; x = cbk; cbk = tmp;
    }

    int mode;
    if (out_size == N_ITEMS * (3 + DIM))      mode = 0;  // [indices | quantized] concat
    else if (out_size == N_ITEMS * DIM)       mode = 1;  // quantized only
    else if (out_size == N_ITEMS * 3)         mode = 2;  // indices only, int32
    else                                       mode = (out_size > N_ITEMS * DIM) ? 0 : 1;

    cudaFuncSetAttribute(rvq_kernel, cudaFuncAttributeMaxDynamicSharedMemorySize, SMEM_BYTES);
    rvq_kernel<<<N_ITEMS / MT, NTHREADS, SMEM_BYTES>>>(x, cbk, (float*)d_out, mode);
}

// round 5
// speedup vs baseline: 2.0228x; 2.0228x over previous
#include <cuda_runtime.h>

#define N_ITEMS  262144
#define DIM      128
#define NCB      3
#define KCW      256
#define MT       64
#define NTHREADS 256
#define RS2      130   // packed-row stride in 8-byte units (1040B: 16B-aligned, conflict-free)

// packed fp32x2 FMA: two independent IEEE fp32 FMA lanes per instruction
#define FMA2(d, a, b) asm("fma.rn.f32x2 %0, %1, %2, %0;" : "+l"(d) : "l"(a), "l"(b))

__device__ float g_cc[NCB * KCW];

// ---- precompute ||c_j||^2 once (double chain, k ascending: identical to prior rounds) ----
__global__ void cc_kernel(const float* __restrict__ codebooks) {
    int stage = blockIdx.x;
    int j = threadIdx.x;
    const float* row = codebooks + ((size_t)stage * KCW + j) * DIM;
    double s = 0.0;
    #pragma unroll 8
    for (int k = 0; k < DIM; k++) { double v = (double)row[k]; s += v * v; }
    g_cc[stage * KCW + j] = (float)s;
}

// smem layout (bytes)
#define OFF_CBP   0                         // 128 pair-rows * RS2 * 8  = 133120
#define OFF_RRES  133120                    // 64 rows * RS2 * 8        =  66560
#define OFF_RRD   199680                    // 64*4 doubles             =   2048
#define OFF_REDV  201728                    // 64*32 float              =   8192
#define OFF_REDI  209920                    // 64*32 int                =   8192
#define OFF_CCS   218112                    // 256 float                =   1024
#define OFF_RRS   219136                    // 64 float                 =    256
#define OFF_BEST  219392                    // 3*64 int                 =    768
#define SMEM_BYTES 220160

__global__ __launch_bounds__(NTHREADS, 1)
void rvq_kernel(const float* __restrict__ x,
                const float* __restrict__ codebooks,
                float* __restrict__ out, int mode)
{
    extern __shared__ char smem[];
    unsigned long long* cbp   = (unsigned long long*)(smem + OFF_CBP);
    unsigned long long* rres2 = (unsigned long long*)(smem + OFF_RRES);
    double* rrd  = (double*)(smem + OFF_RRD);
    float*  redv = (float*)(smem + OFF_REDV);
    int*    redi = (int*)(smem + OFF_REDI);
    float*  cc_s = (float*)(smem + OFF_CCS);
    float*  rrs  = (float*)(smem + OFF_RRS);
    int*    best = (int*)(smem + OFF_BEST);

    const int t  = threadIdx.x;
    const int ig = t & 7;     // items ig + 8u, u<8
    const int cg = t >> 3;    // cw pairs p = cg + 32*v2, v2<4 -> cws {2p, 2p+1}
    const int itemBase = blockIdx.x * MT;

    // ---- init rres2 = (x, x) doubled pairs ----
    {
        const float4* xg = (const float4*)(x + (size_t)itemBase * DIM);
        #pragma unroll
        for (int n = 0; n < 8; n++) {
            int idx = t + NTHREADS * n;      // 0..2047
            int row = idx >> 5;
            int c4  = idx & 31;
            float4 v = xg[idx];
            float2* d = (float2*)&rres2[row * RS2 + c4 * 4];
            d[0] = make_float2(v.x, v.x);
            d[1] = make_float2(v.y, v.y);
            d[2] = make_float2(v.z, v.z);
            d[3] = make_float2(v.w, v.w);
        }
    }

    for (int stage = 0; stage < NCB; stage++) {
        __syncthreads();
        // ---- build packed codebook: cbp[p][k] = (c_{2p}[k], c_{2p+1}[k]) ----
        {
            const float4* cgm = (const float4*)(codebooks + (size_t)stage * KCW * DIM);
            #pragma unroll
            for (int n = 0; n < 16; n++) {
                int idx = t + NTHREADS * n;  // 0..4095
                int p  = idx >> 5;
                int c4 = idx & 31;
                float4 a = cgm[(2 * p)     * (DIM / 4) + c4];
                float4 b = cgm[(2 * p + 1) * (DIM / 4) + c4];
                float2* d = (float2*)&cbp[p * RS2 + c4 * 4];
                d[0] = make_float2(a.x, b.x);
                d[1] = make_float2(a.y, b.y);
                d[2] = make_float2(a.z, b.z);
                d[3] = make_float2(a.w, b.w);
            }
            cc_s[t] = g_cc[stage * KCW + t];
        }
        // ---- rrs partials: 4 threads/item, 32-deep double chains ----
        {
            int item = t >> 2, part = t & 3;
            const float2* rp = (const float2*)&rres2[item * RS2];
            double s = 0.0;
            #pragma unroll 8
            for (int k = part * 32; k < part * 32 + 32; k++) {
                double v = (double)rp[k].x; s += v * v;
            }
            rrd[t] = s;
        }
        __syncthreads();
        if (t < MT) {
            double s = ((rrd[4 * t] + rrd[4 * t + 1]) + rrd[4 * t + 2]) + rrd[4 * t + 3];
            rrs[t] = (float)s;
        }

        // ---- dot tile: acc2[u][v2] = packed (r_i . c_{2p}, r_i . c_{2p+1}) ----
        // Each f32x2 lane is a strict sequential FMA chain over k ascending.
        unsigned long long acc2[8][4];
        #pragma unroll
        for (int u = 0; u < 8; u++)
            #pragma unroll
            for (int v2 = 0; v2 < 4; v2++) acc2[u][v2] = 0ULL;

        const unsigned long long* rbase = &rres2[ig * RS2];
        const unsigned long long* cbase = &cbp[cg * RS2];

        ulonglong2 Ar[8], Ac[4], Br[8], Bc[4];

        auto LOADH = [&](ulonglong2* R, ulonglong2* C, int h) {
            #pragma unroll
            for (int u = 0; u < 8; u++)
                R[u] = *(const ulonglong2*)&rbase[u * 8 * RS2 + 2 * h];
            #pragma unroll
            for (int v2 = 0; v2 < 4; v2++)
                C[v2] = *(const ulonglong2*)&cbase[v2 * 32 * RS2 + 2 * h];
        };
        auto FMAH = [&](const ulonglong2* R, const ulonglong2* C) {
            #pragma unroll
            for (int u = 0; u < 8; u++)
                #pragma unroll
                for (int v2 = 0; v2 < 4; v2++)
                    FMA2(acc2[u][v2], R[u].x, C[v2].x);   // k = 2h
            #pragma unroll
            for (int u = 0; u < 8; u++)
                #pragma unroll
                for (int v2 = 0; v2 < 4; v2++)
                    FMA2(acc2[u][v2], R[u].y, C[v2].y);   // k = 2h+1
        };

        LOADH(Ar, Ac, 0);
        #pragma unroll 1
        for (int h = 0; h < DIM / 2 - 2; h += 2) {   // h = 0..60
            LOADH(Br, Bc, h + 1);
            FMAH(Ar, Ac);
            LOADH(Ar, Ac, h + 2);
            FMAH(Br, Bc);
        }
        LOADH(Br, Bc, DIM / 2 - 1);
        FMAH(Ar, Ac);   // h = 62
        FMAH(Br, Bc);   // h = 63

        __syncthreads();   // rrs ready; acc in regs

        // ---- argmin of d2 = fl(fl(rr - 2*dot) + cc), cw ascending per thread ----
        #pragma unroll
        for (int u = 0; u < 8; u++) {
            int item = ig + 8 * u;
            float rrv = rrs[item];
            float bv = 3.0e38f; int bi = KCW;
            #pragma unroll
            for (int v2 = 0; v2 < 4; v2++) {
                float2 dp = *(float2*)&acc2[u][v2];
                int cw = 2 * (cg + 32 * v2);
                float d2a = __fadd_rn(__fmaf_rn(-2.0f, dp.x, rrv), cc_s[cw]);
                if (d2a < bv) { bv = d2a; bi = cw; }
                float d2b = __fadd_rn(__fmaf_rn(-2.0f, dp.y, rrv), cc_s[cw + 1]);
                if (d2b < bv) { bv = d2b; bi = cw + 1; }
            }
            redv[cg * MT + item] = bv;
            redi[cg * MT + item] = bi;
        }
        __syncthreads();

        // ---- reduce 32 slots per item; tie-break: smaller index ----
        if (t < MT) {
            float bv = 3.0e38f; int bi = KCW;
            #pragma unroll 4
            for (int s2 = 0; s2 < 32; s2++) {
                float v  = redv[s2 * MT + t];
                int   i2 = redi[s2 * MT + t];
                if (v < bv || (v == bv && i2 < bi)) { bv = v; bi = i2; }
            }
            best[stage * MT + t] = bi;
            size_t gi = (size_t)(itemBase + t);
            if (mode == 0)      out[gi * 3 + stage] = (float)bi;
            else if (mode == 2) ((int*)out)[gi * 3 + stage] = bi;
        }
        __syncthreads();

        // ---- residual -= chosen codeword (doubled store) ----
        if (stage < NCB - 1) {
            #pragma unroll
            for (int n = 0; n < 16; n++) {
                int e    = t + NTHREADS * n;   // 0..4095
                int item = e >> 6;
                int k2   = e & 63;             // covers k = 2k2, 2k2+1
                int bi   = best[stage * MT + item];
                const float2* cp = (const float2*)&cbp[(bi >> 1) * RS2 + 2 * k2];
                float2 c0 = cp[0], c1 = cp[1];
                float ca = (bi & 1) ? c0.y : c0.x;
                float cb2 = (bi & 1) ? c1.y : c1.x;
                float2* rp = (float2*)&rres2[item * RS2 + 2 * k2];
                float r0 = rp[0].x, r1 = rp[1].x;
                float n0 = __fsub_rn(r0, ca);
                float n1 = __fsub_rn(r1, cb2);
                rp[0] = make_float2(n0, n0);
                rp[1] = make_float2(n1, n1);
            }
        }
    }
    __syncthreads();

    // ---- quantized = (c0[i0] + c1[i1]) + c2[i2], reference order ----
    if (mode != 2) {
        float* outq = (mode == 0) ? (out + (size_t)N_ITEMS * 3) : out;
        float4* oq4 = (float4*)outq;
        const float4* cb4 = (const float4*)codebooks;
        #pragma unroll
        for (int n = 0; n < 8; n++) {
            int e    = t + NTHREADS * n;   // 0..2047
            int item = e >> 5;
            int c4   = e & 31;
            int i0 = best[0 * MT + item];
            int i1 = best[1 * MT + item];
            int i2 = best[2 * MT + item];
            float4 q0 = cb4[(size_t)(0 * KCW + i0) * (DIM / 4) + c4];
            float4 q1 = cb4[(size_t)(1 * KCW + i1) * (DIM / 4) + c4];
            float4 q2 = cb4[(size_t)(2 * KCW + i2) * (DIM / 4) + c4];
            float4 q;
            q.x = __fadd_rn(__fadd_rn(q0.x, q1.x), q2.x);
            q.y = __fadd_rn(__fadd_rn(q0.y, q1.y), q2.y);
            q.z = __fadd_rn(__fadd_rn(q0.z, q1.z), q2.z);
            q.w = __fadd_rn(__fadd_rn(q0.w, q1.w), q2.w);
            oq4[(size_t)itemBase * (DIM / 4) + e] = q;
        }
    }
}

extern "C" void kernel_launch(void* const* d_in, const int* in_sizes, int n_in,
                              void* d_out, int out_size)
{
    const float* x   = (const float*)d_in[0];
    const float* cbk = (const float*)d_in[1];
    if (n_in >= 2 && in_sizes[0] == NCB * KCW * DIM && in_sizes[1] == N_ITEMS * DIM) {
        const float* tmp = x; x = cbk; cbk = tmp;
    }

    int mode;
    if (out_size == N_ITEMS * (3 + DIM))      mode = 0;
    else if (out_size == N_ITEMS * DIM)       mode = 1;
    else if (out_size == N_ITEMS * 3)         mode = 2;
    else                                       mode = (out_size > N_ITEMS * DIM) ? 0 : 1;

    cc_kernel<<<NCB, KCW>>>(cbk);
    cudaFuncSetAttribute(rvq_kernel, cudaFuncAttributeMaxDynamicSharedMemorySize, SMEM_BYTES);
    rvq_kernel<<<N_ITEMS / MT, NTHREADS, SMEM_BYTES>>>(x, cbk, (float*)d_out, mode);
}